// round 1
// baseline (speedup 1.0000x reference)
#include <cuda_runtime.h>
#include <cuda_bf16.h>
#include <math_constants.h>

// ---------------- problem constants ----------------
#define B_MOL 128
#define NA 48
#define NB 96
#define HID 200
#define AFD 39
#define BFD 50        // ATOM_FDIM + BOND_FDIM
#define LPROT 1000
#define C0 50
#define C1 96
#define C2 128
#define C3 200

// ---------------- device scratch (no allocations allowed) ----------------
__device__ float g_bufA[B_MOL * 200 * LPROT];   // embed out (50ch), conv1 out (128ch)
__device__ float g_bufB[B_MOL * 200 * LPROT];   // conv0 out (96ch), conv2 out (200ch)
__device__ float g_emb[B_MOL * HID];
__device__ float g_prot[B_MOL * C3];

// =====================================================================
// MPNN: one block per molecule. smem: binput | msg | tmp (each 96*200 f32)
// =====================================================================
__global__ void mpnn_kernel(const float* __restrict__ fatoms,
                            const float* __restrict__ fbonds,
                            const int*   __restrict__ agraph,
                            const int*   __restrict__ bgraph,
                            const float* __restrict__ W_i,
                            const float* __restrict__ W_h,
                            const float* __restrict__ W_o_w,
                            const float* __restrict__ W_o_b)
{
    extern __shared__ float sm[];
    float* binput = sm;               // 19200
    float* msg    = sm + 19200;       // 19200
    float* tmp    = sm + 38400;       // 19200

    const int b   = blockIdx.x;
    const int tid = threadIdx.x;
    const float* fb = fbonds + (size_t)b * NB * BFD;
    const float* fa = fatoms + (size_t)b * NA * AFD;
    const int*   bg = bgraph + (size_t)b * NB * 6;
    const int*   ag = agraph + (size_t)b * NA * 6;

    // stage fbonds into smem (tmp)
    for (int idx = tid; idx < NB * BFD; idx += 256) tmp[idx] = fb[idx];
    __syncthreads();

    // binput = fb @ W_i ; msg = relu(binput).  4-row register tile.
    for (int idx = tid; idx < (NB / 4) * HID; idx += 256) {
        int h  = idx % HID;
        int i0 = (idx / HID) * 4;
        float a0 = 0.f, a1 = 0.f, a2 = 0.f, a3 = 0.f;
        for (int k = 0; k < BFD; k++) {
            float w = W_i[k * HID + h];
            a0 = fmaf(tmp[(i0 + 0) * BFD + k], w, a0);
            a1 = fmaf(tmp[(i0 + 1) * BFD + k], w, a1);
            a2 = fmaf(tmp[(i0 + 2) * BFD + k], w, a2);
            a3 = fmaf(tmp[(i0 + 3) * BFD + k], w, a3);
        }
        binput[(i0 + 0) * HID + h] = a0; msg[(i0 + 0) * HID + h] = fmaxf(a0, 0.f);
        binput[(i0 + 1) * HID + h] = a1; msg[(i0 + 1) * HID + h] = fmaxf(a1, 0.f);
        binput[(i0 + 2) * HID + h] = a2; msg[(i0 + 2) * HID + h] = fmaxf(a2, 0.f);
        binput[(i0 + 3) * HID + h] = a3; msg[(i0 + 3) * HID + h] = fmaxf(a3, 0.f);
    }
    __syncthreads();

    // DEPTH-1 = 2 message passing iterations
    for (int d = 0; d < 2; d++) {
        // tmp = gather-sum of msg rows
        for (int idx = tid; idx < NB * HID; idx += 256) {
            int i = idx / HID, h = idx - i * HID;
            float s = 0.f;
            #pragma unroll
            for (int j = 0; j < 6; j++) s += msg[bg[i * 6 + j] * HID + h];
            tmp[idx] = s;
        }
        __syncthreads();
        // msg = relu(binput + tmp @ W_h)
        for (int idx = tid; idx < (NB / 4) * HID; idx += 256) {
            int h  = idx % HID;
            int i0 = (idx / HID) * 4;
            float a0 = binput[(i0 + 0) * HID + h];
            float a1 = binput[(i0 + 1) * HID + h];
            float a2 = binput[(i0 + 2) * HID + h];
            float a3 = binput[(i0 + 3) * HID + h];
            for (int k = 0; k < HID; k++) {
                float w = W_h[k * HID + h];
                a0 = fmaf(tmp[(i0 + 0) * HID + k], w, a0);
                a1 = fmaf(tmp[(i0 + 1) * HID + k], w, a1);
                a2 = fmaf(tmp[(i0 + 2) * HID + k], w, a2);
                a3 = fmaf(tmp[(i0 + 3) * HID + k], w, a3);
            }
            msg[(i0 + 0) * HID + h] = fmaxf(a0, 0.f);
            msg[(i0 + 1) * HID + h] = fmaxf(a1, 0.f);
            msg[(i0 + 2) * HID + h] = fmaxf(a2, 0.f);
            msg[(i0 + 3) * HID + h] = fmaxf(a3, 0.f);
        }
        __syncthreads();
    }

    // anei (48x200) into tmp[0:9600]; stage fatoms into tmp[9600:...]
    for (int idx = tid; idx < NA * HID; idx += 256) {
        int a = idx / HID, h = idx - a * HID;
        float s = 0.f;
        #pragma unroll
        for (int j = 0; j < 6; j++) s += msg[ag[a * 6 + j] * HID + h];
        tmp[idx] = s;
    }
    for (int idx = tid; idx < NA * AFD; idx += 256) tmp[NA * HID + idx] = fa[idx];
    __syncthreads();

    // atom_h = relu([fa, anei] @ W_o + b) into binput rows 0..47
    for (int idx = tid; idx < (NA / 4) * HID; idx += 256) {
        int h  = idx % HID;
        int a0i = (idx / HID) * 4;
        float bb = W_o_b[h];
        float a0 = bb, a1 = bb, a2 = bb, a3 = bb;
        const float* fas = tmp + NA * HID;
        for (int k = 0; k < AFD; k++) {
            float w = W_o_w[k * HID + h];
            a0 = fmaf(fas[(a0i + 0) * AFD + k], w, a0);
            a1 = fmaf(fas[(a0i + 1) * AFD + k], w, a1);
            a2 = fmaf(fas[(a0i + 2) * AFD + k], w, a2);
            a3 = fmaf(fas[(a0i + 3) * AFD + k], w, a3);
        }
        for (int k = 0; k < HID; k++) {
            float w = W_o_w[(AFD + k) * HID + h];
            a0 = fmaf(tmp[(a0i + 0) * HID + k], w, a0);
            a1 = fmaf(tmp[(a0i + 1) * HID + k], w, a1);
            a2 = fmaf(tmp[(a0i + 2) * HID + k], w, a2);
            a3 = fmaf(tmp[(a0i + 3) * HID + k], w, a3);
        }
        binput[(a0i + 0) * HID + h] = fmaxf(a0, 0.f);
        binput[(a0i + 1) * HID + h] = fmaxf(a1, 0.f);
        binput[(a0i + 2) * HID + h] = fmaxf(a2, 0.f);
        binput[(a0i + 3) * HID + h] = fmaxf(a3, 0.f);
    }
    __syncthreads();

    // deterministic mean over atoms
    for (int h = tid; h < HID; h += 256) {
        float s = 0.f;
        for (int a = 0; a < NA; a++) s += binput[a * HID + h];
        g_emb[b * HID + h] = s * (1.f / (float)NA);
    }
}

// =====================================================================
// protein embedding gather -> (B, 50, L) channel-major
// =====================================================================
__global__ void embed_kernel(const int* __restrict__ seq,
                             const float* __restrict__ E)
{
    int idx = blockIdx.x * blockDim.x + threadIdx.x;
    const int total = B_MOL * C0 * LPROT;
    if (idx >= total) return;
    int l = idx % LPROT;
    int c = (idx / LPROT) % C0;
    int b = idx / (LPROT * C0);
    g_bufA[idx] = E[seq[b * LPROT + l] * C0 + c];
}

// =====================================================================
// 1D conv + bias + relu, "same" padding, channel-major.
// Block: 256 threads, tile = 64 out-channels x 64 positions, 4x4 register tile.
// =====================================================================
template <int K>
__global__ void conv_relu_kernel(const float* __restrict__ in,
                                 const float* __restrict__ w,
                                 const float* __restrict__ bias,
                                 float* __restrict__ out,
                                 int Cin, int Cout)
{
    extern __shared__ float sin_s[];     // Cin * (64 + K - 1)
    const int LT = 64;
    const int W  = LT + K - 1;
    const int b  = blockIdx.x;
    const int l0 = blockIdx.y * LT;
    const int o0 = blockIdx.z * 64;
    const int tid = threadIdx.x;
    const int tx = tid & 15;     // position group
    const int ty = tid >> 4;     // channel base

    const float* inb = in + (size_t)b * Cin * LPROT;
    for (int idx = tid; idx < Cin * W; idx += 256) {
        int i = idx / W, t = idx - i * W;
        int gl = l0 + t - K / 2;
        sin_s[idx] = (gl >= 0 && gl < LPROT) ? inb[i * LPROT + gl] : 0.f;
    }
    __syncthreads();

    const float* wptr[4];
    bool valid[4];
    #pragma unroll
    for (int rr = 0; rr < 4; rr++) {
        int o = o0 + ty + rr * 16;
        valid[rr] = (o < Cout);
        int oc = valid[rr] ? o : (Cout - 1);
        wptr[rr] = w + (size_t)oc * Cin * K;
    }

    float acc[4][4];
    #pragma unroll
    for (int rr = 0; rr < 4; rr++)
        #pragma unroll
        for (int r = 0; r < 4; r++) acc[rr][r] = 0.f;

    for (int i = 0; i < Cin; i++) {
        const float* srow = sin_s + i * W;
        #pragma unroll
        for (int t = 0; t < K; t++) {
            float wv[4];
            #pragma unroll
            for (int rr = 0; rr < 4; rr++) wv[rr] = wptr[rr][i * K + t];
            #pragma unroll
            for (int r = 0; r < 4; r++) {
                float sv = srow[tx + r * 16 + t];
                #pragma unroll
                for (int rr = 0; rr < 4; rr++) acc[rr][r] = fmaf(wv[rr], sv, acc[rr][r]);
            }
        }
    }

    #pragma unroll
    for (int rr = 0; rr < 4; rr++) {
        if (!valid[rr]) continue;
        int o = o0 + ty + rr * 16;
        float bv = bias[o];
        #pragma unroll
        for (int r = 0; r < 4; r++) {
            int l = l0 + tx + r * 16;
            if (l < LPROT)
                out[((size_t)b * Cout + o) * LPROT + l] = fmaxf(acc[rr][r] + bv, 0.f);
        }
    }
}

// =====================================================================
// max over L per (b, channel): one warp per row
// =====================================================================
__global__ void maxpool_kernel(const float* __restrict__ in, float* __restrict__ out)
{
    int gwarp = (blockIdx.x * blockDim.x + threadIdx.x) >> 5;
    int lane  = threadIdx.x & 31;
    const int rows = B_MOL * C3;
    if (gwarp >= rows) return;
    const float* p = in + (size_t)gwarp * LPROT;
    float m = -CUDART_INF_F;
    for (int l = lane; l < LPROT; l += 32) m = fmaxf(m, p[l]);
    #pragma unroll
    for (int s = 16; s; s >>= 1) m = fmaxf(m, __shfl_xor_sync(0xFFFFFFFFu, m, s));
    if (lane == 0) out[gwarp] = m;
}

// =====================================================================
// FC head: one block per batch row. 400 -> 200 -> 100 -> 1
// =====================================================================
__global__ void fc_kernel(const float* __restrict__ emb,
                          const float* __restrict__ prot,
                          const float* __restrict__ w0, const float* __restrict__ b0,
                          const float* __restrict__ w1, const float* __restrict__ b1,
                          const float* __restrict__ w2, const float* __restrict__ b2,
                          float* __restrict__ out)
{
    __shared__ float x[400];
    __shared__ float h1[200];
    __shared__ float h2[100];
    __shared__ float red[256];
    const int b = blockIdx.x;
    const int tid = threadIdx.x;

    for (int i = tid; i < 200; i += 256) {
        x[i]       = emb[b * 200 + i];
        x[200 + i] = prot[b * 200 + i];
    }
    __syncthreads();
    for (int j = tid; j < 200; j += 256) {
        float s = b0[j];
        for (int k = 0; k < 400; k++) s = fmaf(x[k], w0[k * 200 + j], s);
        h1[j] = fmaxf(s, 0.f);
    }
    __syncthreads();
    for (int j = tid; j < 100; j += 256) {
        float s = b1[j];
        for (int k = 0; k < 200; k++) s = fmaf(h1[k], w1[k * 100 + j], s);
        h2[j] = fmaxf(s, 0.f);
    }
    __syncthreads();
    float s = 0.f;
    for (int k = tid; k < 100; k += 256) s = fmaf(h2[k], w2[k], s);
    red[tid] = s;
    __syncthreads();
    for (int st = 128; st; st >>= 1) {
        if (tid < st) red[tid] += red[tid + st];
        __syncthreads();
    }
    if (tid == 0) out[b] = red[0] + b2[0];
}

// =====================================================================
extern "C" void kernel_launch(void* const* d_in, const int* in_sizes, int n_in,
                              void* d_out, int out_size)
{
    const float* fatoms  = (const float*)d_in[0];
    const float* fbonds  = (const float*)d_in[1];
    const int*   agraph  = (const int*)  d_in[2];
    const int*   bgraph  = (const int*)  d_in[3];
    const int*   seq     = (const int*)  d_in[4];
    const float* W_i     = (const float*)d_in[5];
    const float* W_h     = (const float*)d_in[6];
    const float* W_o_w   = (const float*)d_in[7];
    const float* W_o_b   = (const float*)d_in[8];
    const float* embedP  = (const float*)d_in[9];
    const float* c0w     = (const float*)d_in[10];
    const float* c0b     = (const float*)d_in[11];
    const float* c1w     = (const float*)d_in[12];
    const float* c1b     = (const float*)d_in[13];
    const float* c2w     = (const float*)d_in[14];
    const float* c2b     = (const float*)d_in[15];
    const float* fc0w    = (const float*)d_in[16];
    const float* fc0b    = (const float*)d_in[17];
    const float* fc1w    = (const float*)d_in[18];
    const float* fc1b    = (const float*)d_in[19];
    const float* fc2w    = (const float*)d_in[20];
    const float* fc2b    = (const float*)d_in[21];
    float* out = (float*)d_out;

    float *bufA, *bufB, *emb, *prot;
    cudaGetSymbolAddress((void**)&bufA, g_bufA);
    cudaGetSymbolAddress((void**)&bufB, g_bufB);
    cudaGetSymbolAddress((void**)&emb,  g_emb);
    cudaGetSymbolAddress((void**)&prot, g_prot);

    const int mpnn_smem = 3 * NB * HID * sizeof(float);   // 230400 B
    cudaFuncSetAttribute(mpnn_kernel, cudaFuncAttributeMaxDynamicSharedMemorySize, mpnn_smem);

    // 1. MPNN -> g_emb
    mpnn_kernel<<<B_MOL, 256, mpnn_smem>>>(fatoms, fbonds, agraph, bgraph,
                                           W_i, W_h, W_o_w, W_o_b);

    // 2. protein embedding -> bufA (B,50,L)
    {
        int total = B_MOL * C0 * LPROT;
        embed_kernel<<<(total + 255) / 256, 256>>>(seq, embedP);
    }

    // 3. conv tower
    {
        dim3 g(B_MOL, (LPROT + 63) / 64, (C1 + 63) / 64);
        conv_relu_kernel<3><<<g, 256, C0 * (64 + 2) * sizeof(float)>>>(bufA, c0w, c0b, bufB, C0, C1);
    }
    {
        dim3 g(B_MOL, (LPROT + 63) / 64, (C2 + 63) / 64);
        conv_relu_kernel<5><<<g, 256, C1 * (64 + 4) * sizeof(float)>>>(bufB, c1w, c1b, bufA, C1, C2);
    }
    {
        dim3 g(B_MOL, (LPROT + 63) / 64, (C3 + 63) / 64);
        conv_relu_kernel<7><<<g, 256, C2 * (64 + 6) * sizeof(float)>>>(bufA, c2w, c2b, bufB, C2, C3);
    }

    // 4. adaptive max pool -> g_prot
    {
        int rows = B_MOL * C3;
        int warps_per_block = 256 / 32;
        int blocks = (rows + warps_per_block - 1) / warps_per_block;
        maxpool_kernel<<<blocks, 256>>>(bufB, prot);
    }

    // 5. FC head -> out
    fc_kernel<<<B_MOL, 256>>>(emb, prot, fc0w, fc0b, fc1w, fc1b, fc2w, fc2b, out);
}